// round 1
// baseline (speedup 1.0000x reference)
#include <cuda_runtime.h>
#include <math.h>

// Problem constants
#define CB   256
#define CV   50
#define CN   32
#define CD   128
#define CND  4096
#define CG   1560
#define CL   12
#define CCH  32
#define CCS  10
#define CHH  384
#define CHS  64
#define COUT 128

// ---- scratch (static __device__ arrays; allocation-free rule) ----
__device__ float g_X[(size_t)CB * CV * CND];       // gathered embeddings  (209 MB)
__device__ float g_XO[(size_t)CV * CB * CG];       // precomputed kernel-part of xo (80 MB)
__device__ float g_xo[CB * CG];                    // per-step xo
__device__ float g_c[CB * CHH];
__device__ float g_h[CB * CHH];
__device__ float g_tmph[CCS * CB * CHH];           // circular hidden FIFO
__device__ float g_tmpdis[CCS * CB];               // circular dist FIFO
__device__ float g_ld[CB * CCS];
__device__ float g_theme[CB * CHH];
__device__ float g_lh[CB * CHH * CCS];             // lh[b][h*10+k]
__device__ float g_rnn[CB * CV * CHH];             // local + hnew

__device__ __forceinline__ float sigmoidf(float x) { return 1.0f / (1.0f + expf(-x)); }

// ---- zero recurrent state (must run every launch: graph replays) ----
__global__ void k_init() {
    int total = CB * CHH * 2 + CCS * CB * CHH + CCS * CB;
    for (int i = blockIdx.x * blockDim.x + threadIdx.x; i < total; i += gridDim.x * blockDim.x) {
        if (i < CB * CHH)                       g_c[i] = 0.f;
        else if (i < 2 * CB * CHH)              g_h[i - CB * CHH] = 0.f;
        else if (i < 2 * CB * CHH + CCS * CB * CHH) g_tmph[i - 2 * CB * CHH] = 0.f;
        else                                    g_tmpdis[i - 2 * CB * CHH - CCS * CB * CHH] = 0.f;
    }
}

__global__ void k_outinit(const float* __restrict__ ob, float* __restrict__ out) {
    int i = blockIdx.x * blockDim.x + threadIdx.x;
    if (i < CB * COUT) out[i] = ob[i & (COUT - 1)];
}

// ---- gather: X[b*V+v][n*D+d] = embed[node_ids[b,v,n]][d] ----
__global__ void k_gather(const int* __restrict__ node_ids, const float* __restrict__ embed) {
    int idx = blockIdx.x * blockDim.x + threadIdx.x;   // per float4
    const int total = CB * CV * CN * (CD / 4);
    if (idx >= total) return;
    int d4 = idx & (CD / 4 - 1);
    int rest = idx / (CD / 4);
    int n = rest & (CN - 1);
    int bv = rest / CN;
    int id = node_ids[bv * CN + n];
    float4 v = ((const float4*)embed)[id * (CD / 4) + d4];
    ((float4*)g_X)[(bv * CN + n) * (CD / 4) + d4] = v;
}

// ---- big GEMM: XO[v][b][g] = X[b*V+v] . kw[g][0:4096] + t*kw[g][4096] + kb[g] ----
// 128x64 tile, BK=16, 256 threads, 8x4 register tile
__global__ __launch_bounds__(256) void k_gemm_xo(const float* __restrict__ kw,
                                                 const float* __restrict__ kb,
                                                 const float* __restrict__ time_) {
    __shared__ float As[16][128];
    __shared__ float Bs[16][64];
    const int tid = threadIdx.x;
    const int m0 = blockIdx.x * 128;
    const int n0 = blockIdx.y * 64;
    const int tx = tid & 15, ty = tid >> 4;
    float acc[8][4] = {};
    for (int k0 = 0; k0 < CND; k0 += 16) {
        #pragma unroll
        for (int r = 0; r < 2; r++) {
            int i = tid + r * 256;
            int row = i >> 2, c4 = i & 3;
            float4 v = *(const float4*)(g_X + (size_t)(m0 + row) * CND + k0 + c4 * 4);
            As[c4 * 4 + 0][row] = v.x; As[c4 * 4 + 1][row] = v.y;
            As[c4 * 4 + 2][row] = v.z; As[c4 * 4 + 3][row] = v.w;
        }
        #pragma unroll
        for (int r = 0; r < 4; r++) {
            int i = tid + r * 256;
            int n = i >> 4, kk = i & 15;
            int gg = n0 + n;
            Bs[kk][n] = (gg < CG) ? kw[(size_t)gg * (CND + 1) + k0 + kk] : 0.f;
        }
        __syncthreads();
        #pragma unroll
        for (int k = 0; k < 16; k++) {
            float a[8], b[4];
            #pragma unroll
            for (int i = 0; i < 8; i++) a[i] = As[k][ty * 8 + i];
            #pragma unroll
            for (int j = 0; j < 4; j++) b[j] = Bs[k][tx * 4 + j];
            #pragma unroll
            for (int i = 0; i < 8; i++)
                #pragma unroll
                for (int j = 0; j < 4; j++) acc[i][j] += a[i] * b[j];
        }
        __syncthreads();
    }
    #pragma unroll
    for (int i = 0; i < 8; i++) {
        int r = m0 + ty * 8 + i;
        int b = r / CV, v = r % CV;
        float t = time_[r];   // time[b*V+v] == time_[r]
        #pragma unroll
        for (int j = 0; j < 4; j++) {
            int gg = n0 + tx * 4 + j;
            if (gg < CG)
                g_XO[((size_t)v * CB + b) * CG + gg] =
                    acc[i][j] + t * kw[(size_t)gg * (CND + 1) + CND] + kb[gg];
        }
    }
}

// ---- per-step rec GEMM: xo[b][g] = XO[v][b][g] + h . rw[g][0:384] + t*rw[g][384] + rb[g] ----
// 64x64 tile, BK=16, 256 threads, 4x4 register tile
__global__ __launch_bounds__(256) void k_rec(const float* __restrict__ rw,
                                             const float* __restrict__ rb,
                                             const float* __restrict__ time_, int v) {
    __shared__ float As[16][64];
    __shared__ float Bs[16][64];
    const int tid = threadIdx.x;
    const int m0 = blockIdx.x * 64;
    const int n0 = blockIdx.y * 64;
    const int tx = tid & 15, ty = tid >> 4;
    float acc[4][4] = {};
    for (int k0 = 0; k0 < CHH; k0 += 16) {
        {
            int row = tid >> 2, c4 = tid & 3;
            float4 va = *(const float4*)(g_h + (m0 + row) * CHH + k0 + c4 * 4);
            As[c4 * 4 + 0][row] = va.x; As[c4 * 4 + 1][row] = va.y;
            As[c4 * 4 + 2][row] = va.z; As[c4 * 4 + 3][row] = va.w;
        }
        #pragma unroll
        for (int r = 0; r < 4; r++) {
            int i = tid + r * 256;
            int n = i >> 4, kk = i & 15;
            int gg = n0 + n;
            Bs[kk][n] = (gg < CG) ? rw[gg * (CHH + 1) + k0 + kk] : 0.f;
        }
        __syncthreads();
        #pragma unroll
        for (int k = 0; k < 16; k++) {
            float a[4], b[4];
            #pragma unroll
            for (int i = 0; i < 4; i++) a[i] = As[k][ty * 4 + i];
            #pragma unroll
            for (int j = 0; j < 4; j++) b[j] = Bs[k][tx * 4 + j];
            #pragma unroll
            for (int i = 0; i < 4; i++)
                #pragma unroll
                for (int j = 0; j < 4; j++) acc[i][j] += a[i] * b[j];
        }
        __syncthreads();
    }
    #pragma unroll
    for (int i = 0; i < 4; i++) {
        int bb = m0 + ty * 4 + i;
        float t = time_[bb * CV + v];
        #pragma unroll
        for (int j = 0; j < 4; j++) {
            int gg = n0 + tx * 4 + j;
            if (gg < CG)
                g_xo[bb * CG + gg] = acc[i][j] + t * rw[gg * (CHH + 1) + CHH] + rb[gg]
                                   + g_XO[((size_t)v * CB + bb) * CG + gg];
        }
    }
}

// ---- gate + FIFO + ld + theme + lh kernel: one block per batch row, 384 threads ----
__global__ __launch_bounds__(CHH) void k_gate(const float* __restrict__ sw,
                                              const float* __restrict__ sb,
                                              const float* __restrict__ rsw,
                                              const float* __restrict__ rsb,
                                              int v, float* __restrict__ out) {
    const int b = blockIdx.x;
    const int t = threadIdx.x;           // h index
    const int slot = v % CCS;
    __shared__ float s24[24];
    __shared__ float sfm[CL], sim[CL];
    __shared__ float sld[CCS];
    __shared__ float smh[CHH];
    __shared__ float ss1[CHS];

    const float* xo = g_xo + b * CG;
    if (t < 24) s24[t] = xo[t];
    __syncthreads();

    if (t == 0) {
        // fm = cumsum(softmax(xo[:12]))
        float m1 = s24[0];
        #pragma unroll
        for (int l = 1; l < CL; l++) m1 = fmaxf(m1, s24[l]);
        float e1[CL], sum1 = 0.f;
        #pragma unroll
        for (int l = 0; l < CL; l++) { e1[l] = expf(s24[l] - m1); sum1 += e1[l]; }
        float inv1 = 1.f / sum1, cum = 0.f, fmsum = 0.f;
        #pragma unroll
        for (int l = 0; l < CL; l++) { cum += e1[l] * inv1; sfm[l] = cum; fmsum += cum; }
        // im = reverse-cumsum(softmax(xo[12:24]))
        float m2 = s24[12];
        #pragma unroll
        for (int l = 1; l < CL; l++) m2 = fmaxf(m2, s24[12 + l]);
        float e2[CL], sum2 = 0.f;
        #pragma unroll
        for (int l = 0; l < CL; l++) { e2[l] = expf(s24[12 + l] - m2); sum2 += e2[l]; }
        float inv2 = 1.f / sum2, cum2 = 0.f;
        for (int l = CL - 1; l >= 0; l--) { cum2 += e2[l] * inv2; sim[l] = cum2; }
        float dist = 1.f - fmsum / (float)CL;
        g_tmpdis[slot * CB + b] = dist;
        out[CB * COUT + v * CB + b] = dist;   // dists[v][b]
    }
    __syncthreads();

    // gates: t = l*32 + ch
    {
        int l = t >> 5;
        float f  = sigmoidf(xo[24 + t]);
        float i_ = sigmoidf(xo[24 + CHH + t]);
        float o  = sigmoidf(xo[24 + 2 * CHH + t]);
        float ci = tanhf(xo[24 + 3 * CHH + t]);
        float cl = g_c[b * CHH + t];
        float fmv = sfm[l], imv = sim[l], ov = fmv * imv;
        float cnew = ov * (f * cl + i_ * ci) + (fmv - ov) * cl + (imv - ov) * ci;
        float hnew = o * tanhf(cnew);
        g_c[b * CHH + t] = cnew;
        g_h[b * CHH + t] = hnew;
        g_tmph[(slot * CB + b) * CHH + t] = hnew;
    }
    __syncthreads();

    // ld = softmax(cumsum(tmp_dis over logical k))
    if (t == 0) {
        float cumv[CCS];
        float cum = 0.f;
        #pragma unroll
        for (int k = 0; k < CCS; k++) {
            int s = v - (CCS - 1) + k;
            float d = (s >= 0) ? g_tmpdis[(s % CCS) * CB + b] : 0.f;
            cum += d;
            cumv[k] = cum;
        }
        float mx = cumv[0];
        #pragma unroll
        for (int k = 1; k < CCS; k++) mx = fmaxf(mx, cumv[k]);
        float e[CCS], sum = 0.f;
        #pragma unroll
        for (int k = 0; k < CCS; k++) { e[k] = expf(cumv[k] - mx); sum += e[k]; }
        float inv = 1.f / sum;
        #pragma unroll
        for (int k = 0; k < CCS; k++) { sld[k] = e[k] * inv; g_ld[b * CCS + k] = e[k] * inv; }
    }
    __syncthreads();

    // lh[b][t*10+k] and meanlh
    {
        float mh = 0.f;
        #pragma unroll
        for (int k = 0; k < CCS; k++) {
            int s = v - (CCS - 1) + k;
            float hv = (s >= 0) ? g_tmph[((s % CCS) * CB + b) * CHH + t] : 0.f;
            float lv = hv * sld[k];
            g_lh[(b * CHH + t) * CCS + k] = lv;
            mh += lv;
        }
        smh[t] = mh * (1.f / (float)CCS);
    }
    __syncthreads();

    // theme stage 1: (H)->(HS), relu
    if (t < CHS) {
        float a = sb[t];
        for (int h = 0; h < CHH; h++) a += smh[h] * sw[t * CHH + h];
        ss1[t] = fmaxf(a, 0.f);
    }
    __syncthreads();

    // theme stage 2: (HS)->(H), sigmoid
    {
        float a = rsb[t];
        #pragma unroll
        for (int j = 0; j < CHS; j++) a += ss1[j] * rsw[t * CHS + j];
        g_theme[b * CHH + t] = sigmoidf(a);
    }
}

// ---- conv GEMM: conv[b][o] = lh[b] . conv_w[o] ; rnn[b][v][o] = theme*conv(+cb) + hnew ----
// 64x32 tile, BK=16, 256 threads, 4x2 register tile; K = 3840
__global__ __launch_bounds__(256) void k_conv(const float* __restrict__ cw,
                                              const float* __restrict__ cb, int v) {
    __shared__ float As[16][64];
    __shared__ float Bs[16][32];
    const int tid = threadIdx.x;
    const int m0 = blockIdx.x * 64;
    const int n0 = blockIdx.y * 32;
    const int tx = tid & 15, ty = tid >> 4;
    const int KK = CHH * CCS;   // 3840
    float acc[4][2] = {};
    for (int k0 = 0; k0 < KK; k0 += 16) {
        {
            int row = tid >> 2, c4 = tid & 3;
            float4 va = *(const float4*)(g_lh + (m0 + row) * KK + k0 + c4 * 4);
            As[c4 * 4 + 0][row] = va.x; As[c4 * 4 + 1][row] = va.y;
            As[c4 * 4 + 2][row] = va.z; As[c4 * 4 + 3][row] = va.w;
        }
        #pragma unroll
        for (int r = 0; r < 2; r++) {
            int i = tid + r * 256;
            int n = i >> 4, kk = i & 15;
            Bs[kk][n] = cw[(n0 + n) * KK + k0 + kk];
        }
        __syncthreads();
        #pragma unroll
        for (int k = 0; k < 16; k++) {
            float a[4], b[2];
            #pragma unroll
            for (int i = 0; i < 4; i++) a[i] = As[k][ty * 4 + i];
            #pragma unroll
            for (int j = 0; j < 2; j++) b[j] = Bs[k][tx * 2 + j];
            #pragma unroll
            for (int i = 0; i < 4; i++)
                #pragma unroll
                for (int j = 0; j < 2; j++) acc[i][j] += a[i] * b[j];
        }
        __syncthreads();
    }
    #pragma unroll
    for (int i = 0; i < 4; i++) {
        int bb = m0 + ty * 4 + i;
        #pragma unroll
        for (int j = 0; j < 2; j++) {
            int o = n0 + tx * 2 + j;
            float conv = acc[i][j] + cb[o];
            float local = g_theme[bb * CHH + o] * conv;
            g_rnn[(bb * CV + v) * CHH + o] = local + g_h[bb * CHH + o];
        }
    }
}

// ---- output GEMM: out[b][o] += rnn[b] . out_w[o], split-K with atomics ----
// 64x32 tile, BK=16, 256 threads, 4x2 register tile; K = 19200, split 10
__global__ __launch_bounds__(256) void k_out(const float* __restrict__ ow,
                                             float* __restrict__ out) {
    __shared__ float As[16][64];
    __shared__ float Bs[16][32];
    const int tid = threadIdx.x;
    const int m0 = blockIdx.x * 64;
    const int n0 = blockIdx.y * 32;
    const int KK = CV * CHH;          // 19200
    const int kbase = blockIdx.z * (KK / 10);
    const int tx = tid & 15, ty = tid >> 4;
    float acc[4][2] = {};
    for (int kt = 0; kt < (KK / 10) / 16; kt++) {
        int k0 = kbase + kt * 16;
        {
            int row = tid >> 2, c4 = tid & 3;
            float4 va = *(const float4*)(g_rnn + (size_t)(m0 + row) * KK + k0 + c4 * 4);
            As[c4 * 4 + 0][row] = va.x; As[c4 * 4 + 1][row] = va.y;
            As[c4 * 4 + 2][row] = va.z; As[c4 * 4 + 3][row] = va.w;
        }
        #pragma unroll
        for (int r = 0; r < 2; r++) {
            int i = tid + r * 256;
            int n = i >> 4, kk = i & 15;
            Bs[kk][n] = ow[(size_t)(n0 + n) * KK + k0 + kk];
        }
        __syncthreads();
        #pragma unroll
        for (int k = 0; k < 16; k++) {
            float a[4], b[2];
            #pragma unroll
            for (int i = 0; i < 4; i++) a[i] = As[k][ty * 4 + i];
            #pragma unroll
            for (int j = 0; j < 2; j++) b[j] = Bs[k][tx * 2 + j];
            #pragma unroll
            for (int i = 0; i < 4; i++)
                #pragma unroll
                for (int j = 0; j < 2; j++) acc[i][j] += a[i] * b[j];
        }
        __syncthreads();
    }
    #pragma unroll
    for (int i = 0; i < 4; i++) {
        int bb = m0 + ty * 4 + i;
        #pragma unroll
        for (int j = 0; j < 2; j++) {
            int o = n0 + tx * 2 + j;
            atomicAdd(&out[bb * COUT + o], acc[i][j]);
        }
    }
}

extern "C" void kernel_launch(void* const* d_in, const int* in_sizes, int n_in,
                              void* d_out, int out_size) {
    const int*   node_ids = (const int*)d_in[0];
    const float* time_    = (const float*)d_in[3];
    const float* embed    = (const float*)d_in[6];
    const float* kw  = (const float*)d_in[7];
    const float* kb  = (const float*)d_in[8];
    const float* rw  = (const float*)d_in[9];
    const float* rb  = (const float*)d_in[10];
    const float* sw  = (const float*)d_in[11];
    const float* sb  = (const float*)d_in[12];
    const float* rsw = (const float*)d_in[13];
    const float* rsb = (const float*)d_in[14];
    const float* cw  = (const float*)d_in[15];
    const float* cb  = (const float*)d_in[16];
    const float* ow  = (const float*)d_in[17];
    const float* ob  = (const float*)d_in[18];
    float* out = (float*)d_out;

    k_init<<<1024, 256>>>();
    k_outinit<<<(CB * COUT + 255) / 256, 256>>>(ob, out);
    k_gather<<<(CB * CV * CN * (CD / 4) + 255) / 256, 256>>>(node_ids, embed);
    k_gemm_xo<<<dim3(CB * CV / 128, (CG + 63) / 64), 256>>>(kw, kb, time_);
    for (int v = 0; v < CV; v++) {
        k_rec<<<dim3(CB / 64, (CG + 63) / 64), 256>>>(rw, rb, time_, v);
        k_gate<<<CB, CHH>>>(sw, sb, rsw, rsb, v, out);
        k_conv<<<dim3(CB / 64, CHH / 32), 256>>>(cw, cb, v);
    }
    k_out<<<dim3(CB / 64, COUT / 32, 10), 256>>>(ow, out);
}

// round 2
// speedup vs baseline: 1.5136x; 1.5136x over previous
#include <cuda_runtime.h>
#include <math.h>

#define CB   256
#define CV   50
#define CN   32
#define CD   128
#define CND  4096
#define CG   1560
#define CL   12
#define CCS  10
#define CHH  384
#define CHS  64
#define COUT 128
#define SPLITC 16
#define SPLITO 24

// ---- scratch ----
__device__ float g_XO[(size_t)CV * CB * CG];       // precomputed kernel-part of xo (80 MB)
__device__ float g_xo[CB * CG];
__device__ float g_c[CB * CHH];
__device__ float g_h[CB * CHH];
__device__ float g_tmph[CCS * CB * CHH];
__device__ float g_tmpdis[CCS * CB];
__device__ float g_theme[CB * CHH];
__device__ float g_lh[CB * CHH * CCS];
__device__ float g_rnn[(size_t)CB * CV * CHH];
__device__ float g_convp[(size_t)SPLITC * CB * CHH];

__device__ __forceinline__ float sigmoidf(float x) { return 1.0f / (1.0f + expf(-x)); }

__global__ void k_init() {
    int total = CB * CHH * 2 + CCS * CB * CHH + CCS * CB;
    for (int i = blockIdx.x * blockDim.x + threadIdx.x; i < total; i += gridDim.x * blockDim.x) {
        if (i < CB * CHH)                       g_c[i] = 0.f;
        else if (i < 2 * CB * CHH)              g_h[i - CB * CHH] = 0.f;
        else if (i < 2 * CB * CHH + CCS * CB * CHH) g_tmph[i - 2 * CB * CHH] = 0.f;
        else                                    g_tmpdis[i - 2 * CB * CHH - CCS * CB * CHH] = 0.f;
    }
}

__global__ void k_outinit(const float* __restrict__ ob, float* __restrict__ out) {
    int i = blockIdx.x * blockDim.x + threadIdx.x;
    if (i < CB * COUT) out[i] = ob[i & (COUT - 1)];
}

// ---- big GEMM with fused gather: XO[v][b][g] = embed[ids[r]] . kw[g] + t*kw[g][4096] + kb[g] ----
// BM=128 BN=128 BK=8, 256 threads, 8x8 register tile
__global__ __launch_bounds__(256) void k_gemm_xo(const float* __restrict__ kw,
                                                 const float* __restrict__ kb,
                                                 const float* __restrict__ time_,
                                                 const int* __restrict__ node_ids,
                                                 const float* __restrict__ embed) {
    __shared__ float As[8][128];
    __shared__ float Bs[8][128];
    const int tid = threadIdx.x;
    const int m0 = blockIdx.x * 128, n0 = blockIdx.y * 128;
    const int tx = tid & 15, ty = tid >> 4;
    const int arow = tid >> 1, ac4 = (tid & 1) * 4;
    const int brow = tid >> 1, bc4 = (tid & 1) * 4;
    const int gB = n0 + brow;
    const bool bok = gB < CG;
    const float* kwrow = kw + (size_t)gB * (CND + 1) + bc4;
    const int* nid = node_ids + (m0 + arow) * CN;

    float acc[8][8];
    #pragma unroll
    for (int i = 0; i < 8; i++)
        #pragma unroll
        for (int j = 0; j < 8; j++) acc[i][j] = 0.f;

    for (int nb = 0; nb < CN; nb++) {
        const float* erow = embed + (size_t)nid[nb] * CD + ac4;
        #pragma unroll 1
        for (int kq = 0; kq < CD / 8; kq++) {
            const int k0 = nb * CD + kq * 8;
            float4 va = *(const float4*)(erow + kq * 8);
            float b0 = 0.f, b1 = 0.f, b2 = 0.f, b3 = 0.f;
            if (bok) { const float* p = kwrow + k0; b0 = p[0]; b1 = p[1]; b2 = p[2]; b3 = p[3]; }
            As[ac4 + 0][arow] = va.x; As[ac4 + 1][arow] = va.y;
            As[ac4 + 2][arow] = va.z; As[ac4 + 3][arow] = va.w;
            Bs[bc4 + 0][brow] = b0; Bs[bc4 + 1][brow] = b1;
            Bs[bc4 + 2][brow] = b2; Bs[bc4 + 3][brow] = b3;
            __syncthreads();
            #pragma unroll
            for (int k = 0; k < 8; k++) {
                float4 a0 = *(const float4*)&As[k][ty * 8];
                float4 a1 = *(const float4*)&As[k][ty * 8 + 4];
                float4 c0 = *(const float4*)&Bs[k][tx * 8];
                float4 c1 = *(const float4*)&Bs[k][tx * 8 + 4];
                float av[8] = {a0.x, a0.y, a0.z, a0.w, a1.x, a1.y, a1.z, a1.w};
                float bv[8] = {c0.x, c0.y, c0.z, c0.w, c1.x, c1.y, c1.z, c1.w};
                #pragma unroll
                for (int i = 0; i < 8; i++)
                    #pragma unroll
                    for (int j = 0; j < 8; j++) acc[i][j] += av[i] * bv[j];
            }
            __syncthreads();
        }
    }
    #pragma unroll
    for (int i = 0; i < 8; i++) {
        int r = m0 + ty * 8 + i;
        int b = r / CV, v = r - b * CV;
        float t = time_[r];
        #pragma unroll
        for (int j = 0; j < 8; j++) {
            int g = n0 + tx * 8 + j;
            if (g < CG)
                g_XO[((size_t)v * CB + b) * CG + g] =
                    acc[i][j] + t * kw[(size_t)g * (CND + 1) + CND] + kb[g];
        }
    }
}

// ---- per-step rec GEMM: BM=64 BN=128 BK=8, 256 threads, 4x8 tile ----
__global__ __launch_bounds__(256) void k_rec(const float* __restrict__ rw,
                                             const float* __restrict__ rb,
                                             const float* __restrict__ time_, int v) {
    __shared__ float As[8][64];
    __shared__ float Bs[8][128];
    const int tid = threadIdx.x;
    const int m0 = blockIdx.x * 64, n0 = blockIdx.y * 128;
    const int tx = tid & 15, ty = tid >> 4;
    const int arow = tid >> 2, ac2 = (tid & 3) * 2;
    float acc[4][8];
    #pragma unroll
    for (int i = 0; i < 4; i++)
        #pragma unroll
        for (int j = 0; j < 8; j++) acc[i][j] = 0.f;

    for (int k0 = 0; k0 < CHH; k0 += 8) {
        float2 va = *(const float2*)(g_h + (m0 + arow) * CHH + k0 + ac2);
        float bvals[4];
        #pragma unroll
        for (int r = 0; r < 4; r++) {
            int s = tid + 256 * r;
            int n = s >> 3, k = s & 7;
            int g = n0 + n;
            bvals[r] = (g < CG) ? rw[(size_t)g * (CHH + 1) + k0 + k] : 0.f;
        }
        As[ac2 + 0][arow] = va.x;
        As[ac2 + 1][arow] = va.y;
        #pragma unroll
        for (int r = 0; r < 4; r++) {
            int s = tid + 256 * r;
            Bs[s & 7][s >> 3] = bvals[r];
        }
        __syncthreads();
        #pragma unroll
        for (int k = 0; k < 8; k++) {
            float4 a = *(const float4*)&As[k][ty * 4];
            float4 c0 = *(const float4*)&Bs[k][tx * 8];
            float4 c1 = *(const float4*)&Bs[k][tx * 8 + 4];
            float av[4] = {a.x, a.y, a.z, a.w};
            float bv[8] = {c0.x, c0.y, c0.z, c0.w, c1.x, c1.y, c1.z, c1.w};
            #pragma unroll
            for (int i = 0; i < 4; i++)
                #pragma unroll
                for (int j = 0; j < 8; j++) acc[i][j] += av[i] * bv[j];
        }
        __syncthreads();
    }
    #pragma unroll
    for (int i = 0; i < 4; i++) {
        int bb = m0 + ty * 4 + i;
        float t = time_[bb * CV + v];
        const float* xop = g_XO + ((size_t)v * CB + bb) * CG;
        #pragma unroll
        for (int j = 0; j < 8; j++) {
            int g = n0 + tx * 8 + j;
            if (g < CG)
                g_xo[bb * CG + g] = acc[i][j] + t * rw[(size_t)g * (CHH + 1) + CHH]
                                  + rb[g] + xop[g];
        }
    }
}

// ---- gate + FIFO + ld + theme + lh + (prev-step conv combine) ----
__global__ __launch_bounds__(CHH) void k_gate(const float* __restrict__ sw,
                                              const float* __restrict__ sb,
                                              const float* __restrict__ rsw,
                                              const float* __restrict__ rsb,
                                              const float* __restrict__ cb,
                                              int v, float* __restrict__ out) {
    const int b = blockIdx.x;
    const int t = threadIdx.x;
    const int slot = v % CCS;
    __shared__ float s24[24];
    __shared__ float sfm[CL], sim[CL];
    __shared__ float sld[CCS];
    __shared__ float smh[CHH];
    __shared__ float ss1[CHS];
    __shared__ float red[6][CHS];

    // combine step v-1: rnn[b][v-1] = theme * (conv + cb) + hnew   (reads state of step v-1)
    if (v > 0) {
        float s = 0.f;
        #pragma unroll
        for (int z = 0; z < SPLITC; z++) s += g_convp[((size_t)z * CB + b) * CHH + t];
        g_rnn[((size_t)b * CV + (v - 1)) * CHH + t] =
            g_theme[b * CHH + t] * (s + cb[t]) + g_h[b * CHH + t];
    }

    const float* xo = g_xo + b * CG;
    if (t < 24) s24[t] = xo[t];
    __syncthreads();

    if (t == 0) {
        float m1 = s24[0];
        #pragma unroll
        for (int l = 1; l < CL; l++) m1 = fmaxf(m1, s24[l]);
        float e1[CL], sum1 = 0.f;
        #pragma unroll
        for (int l = 0; l < CL; l++) { e1[l] = expf(s24[l] - m1); sum1 += e1[l]; }
        float inv1 = 1.f / sum1, cum = 0.f, fmsum = 0.f;
        #pragma unroll
        for (int l = 0; l < CL; l++) { cum += e1[l] * inv1; sfm[l] = cum; fmsum += cum; }
        float m2 = s24[12];
        #pragma unroll
        for (int l = 1; l < CL; l++) m2 = fmaxf(m2, s24[12 + l]);
        float e2[CL], sum2 = 0.f;
        #pragma unroll
        for (int l = 0; l < CL; l++) { e2[l] = expf(s24[12 + l] - m2); sum2 += e2[l]; }
        float inv2 = 1.f / sum2, cum2 = 0.f;
        for (int l = CL - 1; l >= 0; l--) { cum2 += e2[l] * inv2; sim[l] = cum2; }
        float dist = 1.f - fmsum / (float)CL;
        g_tmpdis[slot * CB + b] = dist;
        out[CB * COUT + v * CB + b] = dist;
    }
    __syncthreads();

    {
        int l = t >> 5;
        float f  = sigmoidf(xo[24 + t]);
        float i_ = sigmoidf(xo[24 + CHH + t]);
        float o  = sigmoidf(xo[24 + 2 * CHH + t]);
        float ci = tanhf(xo[24 + 3 * CHH + t]);
        float cl = g_c[b * CHH + t];
        float fmv = sfm[l], imv = sim[l], ov = fmv * imv;
        float cnew = ov * (f * cl + i_ * ci) + (fmv - ov) * cl + (imv - ov) * ci;
        float hnew = o * tanhf(cnew);
        g_c[b * CHH + t] = cnew;
        g_h[b * CHH + t] = hnew;
        g_tmph[(slot * CB + b) * CHH + t] = hnew;
    }
    __syncthreads();

    if (t == 0) {
        float cumv[CCS];
        float cum = 0.f;
        #pragma unroll
        for (int k = 0; k < CCS; k++) {
            int s = v - (CCS - 1) + k;
            float d = (s >= 0) ? g_tmpdis[(s % CCS) * CB + b] : 0.f;
            cum += d;
            cumv[k] = cum;
        }
        float mx = cumv[0];
        #pragma unroll
        for (int k = 1; k < CCS; k++) mx = fmaxf(mx, cumv[k]);
        float e[CCS], sum = 0.f;
        #pragma unroll
        for (int k = 0; k < CCS; k++) { e[k] = expf(cumv[k] - mx); sum += e[k]; }
        float inv = 1.f / sum;
        #pragma unroll
        for (int k = 0; k < CCS; k++) sld[k] = e[k] * inv;
    }
    __syncthreads();

    {
        float mh = 0.f;
        #pragma unroll
        for (int k = 0; k < CCS; k++) {
            int s = v - (CCS - 1) + k;
            float hv = (s >= 0) ? g_tmph[((s % CCS) * CB + b) * CHH + t] : 0.f;
            float lv = hv * sld[k];
            g_lh[(b * CHH + t) * CCS + k] = lv;
            mh += lv;
        }
        smh[t] = mh * (1.f / (float)CCS);
    }
    __syncthreads();

    // theme stage 1 parallel over all 384 threads (6 segments x 64 outputs)
    {
        int j = t & 63, seg = t >> 6;
        float p = 0.f;
        #pragma unroll
        for (int h = 0; h < 64; h++) p += smh[seg * 64 + h] * sw[j * CHH + seg * 64 + h];
        red[seg][j] = p;
    }
    __syncthreads();
    if (t < CHS) {
        float a = sb[t];
        #pragma unroll
        for (int z = 0; z < 6; z++) a += red[z][t];
        ss1[t] = fmaxf(a, 0.f);
    }
    __syncthreads();

    {
        float a = rsb[t];
        #pragma unroll
        for (int j = 0; j < CHS; j++) a += ss1[j] * rsw[t * CHS + j];
        g_theme[b * CHH + t] = sigmoidf(a);
    }
}

// ---- conv GEMM (split-K to partials): BM=128 BN=128 BK=8, 8x8 tile ----
__global__ __launch_bounds__(256) void k_conv(const float* __restrict__ cw) {
    __shared__ float As[8][128];
    __shared__ float Bs[8][128];
    const int tid = threadIdx.x;
    const int m0 = blockIdx.x * 128, n0 = blockIdx.y * 128;
    const int tx = tid & 15, ty = tid >> 4;
    const int arow = tid >> 1, ac4 = (tid & 1) * 4;
    const int KK = CHH * CCS;
    const int kbase = blockIdx.z * (KK / SPLITC);
    float acc[8][8];
    #pragma unroll
    for (int i = 0; i < 8; i++)
        #pragma unroll
        for (int j = 0; j < 8; j++) acc[i][j] = 0.f;

    for (int kt = 0; kt < (KK / SPLITC) / 8; kt++) {
        int k0 = kbase + kt * 8;
        float4 va = *(const float4*)(g_lh + (size_t)(m0 + arow) * KK + k0 + ac4);
        float4 vb = *(const float4*)(cw + (size_t)(n0 + arow) * KK + k0 + ac4);
        As[ac4 + 0][arow] = va.x; As[ac4 + 1][arow] = va.y;
        As[ac4 + 2][arow] = va.z; As[ac4 + 3][arow] = va.w;
        Bs[ac4 + 0][arow] = vb.x; Bs[ac4 + 1][arow] = vb.y;
        Bs[ac4 + 2][arow] = vb.z; Bs[ac4 + 3][arow] = vb.w;
        __syncthreads();
        #pragma unroll
        for (int k = 0; k < 8; k++) {
            float4 a0 = *(const float4*)&As[k][ty * 8];
            float4 a1 = *(const float4*)&As[k][ty * 8 + 4];
            float4 c0 = *(const float4*)&Bs[k][tx * 8];
            float4 c1 = *(const float4*)&Bs[k][tx * 8 + 4];
            float av[8] = {a0.x, a0.y, a0.z, a0.w, a1.x, a1.y, a1.z, a1.w};
            float bv[8] = {c0.x, c0.y, c0.z, c0.w, c1.x, c1.y, c1.z, c1.w};
            #pragma unroll
            for (int i = 0; i < 8; i++)
                #pragma unroll
                for (int j = 0; j < 8; j++) acc[i][j] += av[i] * bv[j];
        }
        __syncthreads();
    }
    #pragma unroll
    for (int i = 0; i < 8; i++) {
        int bb = m0 + ty * 8 + i;
        #pragma unroll
        for (int j = 0; j < 8; j++) {
            int o = n0 + tx * 8 + j;
            g_convp[((size_t)blockIdx.z * CB + bb) * CHH + o] = acc[i][j];
        }
    }
}

// ---- final combine for v = V-1 ----
__global__ void k_comb_last(const float* __restrict__ cb) {
    int idx = blockIdx.x * blockDim.x + threadIdx.x;
    if (idx >= CB * CHH) return;
    int bb = idx / CHH, o = idx - bb * CHH;
    float s = 0.f;
    #pragma unroll
    for (int z = 0; z < SPLITC; z++) s += g_convp[((size_t)z * CB + bb) * CHH + o];
    g_rnn[((size_t)bb * CV + (CV - 1)) * CHH + o] = g_theme[idx] * (s + cb[o]) + g_h[idx];
}

// ---- output GEMM: BM=64 BN=128 BK=8, 4x8 tile, split-K=24 with atomics ----
__global__ __launch_bounds__(256) void k_out(const float* __restrict__ ow,
                                             float* __restrict__ out) {
    __shared__ float As[8][64];
    __shared__ float Bs[8][128];
    const int tid = threadIdx.x;
    const int m0 = blockIdx.x * 64;
    const int KK = CV * CHH;
    const int kbase = blockIdx.z * (KK / SPLITO);
    const int tx = tid & 15, ty = tid >> 4;
    const int arow = tid >> 2, ac2 = (tid & 3) * 2;
    const int brow = tid >> 1, bc4 = (tid & 1) * 4;
    float acc[4][8];
    #pragma unroll
    for (int i = 0; i < 4; i++)
        #pragma unroll
        for (int j = 0; j < 8; j++) acc[i][j] = 0.f;

    for (int kt = 0; kt < (KK / SPLITO) / 8; kt++) {
        int k0 = kbase + kt * 8;
        float2 va = *(const float2*)(g_rnn + (size_t)(m0 + arow) * KK + k0 + ac2);
        float4 vb = *(const float4*)(ow + (size_t)brow * KK + k0 + bc4);
        As[ac2 + 0][arow] = va.x;
        As[ac2 + 1][arow] = va.y;
        Bs[bc4 + 0][brow] = vb.x; Bs[bc4 + 1][brow] = vb.y;
        Bs[bc4 + 2][brow] = vb.z; Bs[bc4 + 3][brow] = vb.w;
        __syncthreads();
        #pragma unroll
        for (int k = 0; k < 8; k++) {
            float4 a = *(const float4*)&As[k][ty * 4];
            float4 c0 = *(const float4*)&Bs[k][tx * 8];
            float4 c1 = *(const float4*)&Bs[k][tx * 8 + 4];
            float av[4] = {a.x, a.y, a.z, a.w};
            float bv[8] = {c0.x, c0.y, c0.z, c0.w, c1.x, c1.y, c1.z, c1.w};
            #pragma unroll
            for (int i = 0; i < 4; i++)
                #pragma unroll
                for (int j = 0; j < 8; j++) acc[i][j] += av[i] * bv[j];
        }
        __syncthreads();
    }
    #pragma unroll
    for (int i = 0; i < 4; i++) {
        int bb = m0 + ty * 4 + i;
        #pragma unroll
        for (int j = 0; j < 8; j++) {
            atomicAdd(&out[bb * COUT + tx * 8 + j], acc[i][j]);
        }
    }
}

extern "C" void kernel_launch(void* const* d_in, const int* in_sizes, int n_in,
                              void* d_out, int out_size) {
    const int*   node_ids = (const int*)d_in[0];
    const float* time_    = (const float*)d_in[3];
    const float* embed    = (const float*)d_in[6];
    const float* kw  = (const float*)d_in[7];
    const float* kb  = (const float*)d_in[8];
    const float* rw  = (const float*)d_in[9];
    const float* rb  = (const float*)d_in[10];
    const float* sw  = (const float*)d_in[11];
    const float* sb  = (const float*)d_in[12];
    const float* rsw = (const float*)d_in[13];
    const float* rsb = (const float*)d_in[14];
    const float* cw  = (const float*)d_in[15];
    const float* cb  = (const float*)d_in[16];
    const float* ow  = (const float*)d_in[17];
    const float* ob  = (const float*)d_in[18];
    float* out = (float*)d_out;

    k_init<<<512, 256>>>();
    k_outinit<<<(CB * COUT + 255) / 256, 256>>>(ob, out);
    k_gemm_xo<<<dim3(CB * CV / 128, (CG + 127) / 128), 256>>>(kw, kb, time_, node_ids, embed);
    for (int v = 0; v < CV; v++) {
        k_rec<<<dim3(CB / 64, (CG + 127) / 128), 256>>>(rw, rb, time_, v);
        k_gate<<<CB, CHH>>>(sw, sb, rsw, rsb, cb, v, out);
        k_conv<<<dim3(CB / 128, CHH / 128, SPLITC), 256>>>(cw);
    }
    k_comb_last<<<(CB * CHH + 255) / 256, 256>>>(cb);
    k_out<<<dim3(CB / 64, 1, SPLITO), 256>>>(ow, out);
}

// round 3
// speedup vs baseline: 1.9857x; 1.3120x over previous
#include <cuda_runtime.h>
#include <math.h>

#define CB   256
#define CV   50
#define CN   32
#define CD   128
#define CND  4096
#define CG   1560
#define CL   12
#define CCS  10
#define CHH  384
#define CHS  64
#define COUT 128
#define CKLH (CHH * CCS)          // 3840
#define SPLITO 24

// ---- scratch ----
__device__ float g_XO[(size_t)CV * CB * CG];          // 80 MB
__device__ float g_xo[CB * CG];
__device__ float g_c[CB * CHH];
__device__ float g_h[CB * CHH];
__device__ float g_tmpdis[CCS * CB];
__device__ float g_h_all[(size_t)CV * CB * CHH];      // 19.7 MB
__device__ float g_theme_all[(size_t)CV * CB * CHH];  // 19.7 MB
__device__ float g_lh_all[(size_t)CV * CB * CKLH];    // 196.6 MB
__device__ float g_rnn[(size_t)CB * CV * CHH];        // 19.7 MB

__device__ __forceinline__ float sigmoidf(float x) { return 1.0f / (1.0f + expf(-x)); }

__global__ void k_init() {
    int i = blockIdx.x * blockDim.x + threadIdx.x;
    if (i < CB * CHH) { g_c[i] = 0.f; g_h[i] = 0.f; }
}

__global__ void k_outinit(const float* __restrict__ ob, float* __restrict__ out) {
    int i = blockIdx.x * blockDim.x + threadIdx.x;
    if (i < CB * COUT) out[i] = ob[i & (COUT - 1)];
}

// ---- big GEMM with fused gather: XO[v][b][g] ----
__global__ __launch_bounds__(256) void k_gemm_xo(const float* __restrict__ kw,
                                                 const float* __restrict__ kb,
                                                 const float* __restrict__ time_,
                                                 const int* __restrict__ node_ids,
                                                 const float* __restrict__ embed) {
    __shared__ float As[8][128];
    __shared__ float Bs[8][128];
    const int tid = threadIdx.x;
    const int m0 = blockIdx.x * 128, n0 = blockIdx.y * 128;
    const int tx = tid & 15, ty = tid >> 4;
    const int arow = tid >> 1, ac4 = (tid & 1) * 4;
    const int brow = tid >> 1, bc4 = (tid & 1) * 4;
    const int gB = n0 + brow;
    const bool bok = gB < CG;
    const float* kwrow = kw + (size_t)gB * (CND + 1) + bc4;
    const int* nid = node_ids + (m0 + arow) * CN;

    float acc[8][8];
    #pragma unroll
    for (int i = 0; i < 8; i++)
        #pragma unroll
        for (int j = 0; j < 8; j++) acc[i][j] = 0.f;

    for (int nb = 0; nb < CN; nb++) {
        const float* erow = embed + (size_t)nid[nb] * CD + ac4;
        #pragma unroll 1
        for (int kq = 0; kq < CD / 8; kq++) {
            const int k0 = nb * CD + kq * 8;
            float4 va = *(const float4*)(erow + kq * 8);
            float b0 = 0.f, b1 = 0.f, b2 = 0.f, b3 = 0.f;
            if (bok) { const float* p = kwrow + k0; b0 = p[0]; b1 = p[1]; b2 = p[2]; b3 = p[3]; }
            As[ac4 + 0][arow] = va.x; As[ac4 + 1][arow] = va.y;
            As[ac4 + 2][arow] = va.z; As[ac4 + 3][arow] = va.w;
            Bs[bc4 + 0][brow] = b0; Bs[bc4 + 1][brow] = b1;
            Bs[bc4 + 2][brow] = b2; Bs[bc4 + 3][brow] = b3;
            __syncthreads();
            #pragma unroll
            for (int k = 0; k < 8; k++) {
                float4 a0 = *(const float4*)&As[k][ty * 8];
                float4 a1 = *(const float4*)&As[k][ty * 8 + 4];
                float4 c0 = *(const float4*)&Bs[k][tx * 8];
                float4 c1 = *(const float4*)&Bs[k][tx * 8 + 4];
                float av[8] = {a0.x, a0.y, a0.z, a0.w, a1.x, a1.y, a1.z, a1.w};
                float bv[8] = {c0.x, c0.y, c0.z, c0.w, c1.x, c1.y, c1.z, c1.w};
                #pragma unroll
                for (int i = 0; i < 8; i++)
                    #pragma unroll
                    for (int j = 0; j < 8; j++) acc[i][j] += av[i] * bv[j];
            }
            __syncthreads();
        }
    }
    #pragma unroll
    for (int i = 0; i < 8; i++) {
        int r = m0 + ty * 8 + i;
        int b = r / CV, v = r - b * CV;
        float t = time_[r];
        #pragma unroll
        for (int j = 0; j < 8; j++) {
            int g = n0 + tx * 8 + j;
            if (g < CG)
                g_XO[((size_t)v * CB + b) * CG + g] =
                    acc[i][j] + t * kw[(size_t)g * (CND + 1) + CND] + kb[g];
        }
    }
}

// ---- per-step rec GEMM: BM=32(b) BN=64(g) BK=16, 128 threads, 4x4 tile, 200 blocks ----
__global__ __launch_bounds__(128) void k_rec(const float* __restrict__ rw,
                                             const float* __restrict__ rb,
                                             const float* __restrict__ time_, int v) {
    __shared__ float As[16][36];
    __shared__ float Bs[16][64];
    const int tid = threadIdx.x;
    const int m0 = blockIdx.x * 32, n0 = blockIdx.y * 64;
    const int tx = tid & 15, ty = tid >> 4;      // tx: g groups (16x4), ty: b groups (8x4)
    const int arow = tid >> 2, ac4 = (tid & 3) * 4;
    const int bn = tid >> 1, bk0 = (tid & 1) * 8;
    const int gB = n0 + bn;
    const bool bok = gB < CG;
    const float* rwp = rw + (size_t)gB * (CHH + 1);

    float acc[4][4];
    #pragma unroll
    for (int i = 0; i < 4; i++)
        #pragma unroll
        for (int j = 0; j < 4; j++) acc[i][j] = 0.f;

    for (int k0 = 0; k0 < CHH; k0 += 16) {
        float4 va = *(const float4*)(g_h + (m0 + arow) * CHH + k0 + ac4);
        float bv[8];
        #pragma unroll
        for (int i = 0; i < 8; i++) bv[i] = bok ? rwp[k0 + bk0 + i] : 0.f;
        As[ac4 + 0][arow] = va.x; As[ac4 + 1][arow] = va.y;
        As[ac4 + 2][arow] = va.z; As[ac4 + 3][arow] = va.w;
        #pragma unroll
        for (int i = 0; i < 8; i++) Bs[bk0 + i][bn] = bv[i];
        __syncthreads();
        #pragma unroll
        for (int k = 0; k < 16; k++) {
            float4 a = *(const float4*)&As[k][ty * 4];
            float4 b = *(const float4*)&Bs[k][tx * 4];
            float av[4] = {a.x, a.y, a.z, a.w};
            float bb[4] = {b.x, b.y, b.z, b.w};
            #pragma unroll
            for (int i = 0; i < 4; i++)
                #pragma unroll
                for (int j = 0; j < 4; j++) acc[i][j] += av[i] * bb[j];
        }
        __syncthreads();
    }
    #pragma unroll
    for (int i = 0; i < 4; i++) {
        int bb = m0 + ty * 4 + i;
        float t = time_[bb * CV + v];
        const float* xop = g_XO + ((size_t)v * CB + bb) * CG;
        #pragma unroll
        for (int j = 0; j < 4; j++) {
            int g = n0 + tx * 4 + j;
            if (g < CG)
                g_xo[bb * CG + g] = acc[i][j] + t * rw[(size_t)g * (CHH + 1) + CHH]
                                  + rb[g] + xop[g];
        }
    }
}

// ---- gate + FIFO + ld + theme + lh: one block per batch row ----
__global__ __launch_bounds__(CHH) void k_gate(const float* __restrict__ sw,
                                              const float* __restrict__ sb,
                                              const float* __restrict__ rsw,
                                              const float* __restrict__ rsb,
                                              int v, float* __restrict__ out) {
    const int b = blockIdx.x;
    const int t = threadIdx.x;
    const int slot = v % CCS;
    __shared__ float s24[24];
    __shared__ float sfm[CL], sim[CL];
    __shared__ float sld[CCS];
    __shared__ float smh[CHH];
    __shared__ float ss1[CHS];
    __shared__ float red[6][CHS];

    const float* xo = g_xo + b * CG;
    if (t < 24) s24[t] = xo[t];
    __syncthreads();

    if (t == 0) {
        float m1 = s24[0];
        #pragma unroll
        for (int l = 1; l < CL; l++) m1 = fmaxf(m1, s24[l]);
        float e1[CL], sum1 = 0.f;
        #pragma unroll
        for (int l = 0; l < CL; l++) { e1[l] = expf(s24[l] - m1); sum1 += e1[l]; }
        float inv1 = 1.f / sum1, cum = 0.f, fmsum = 0.f;
        #pragma unroll
        for (int l = 0; l < CL; l++) { cum += e1[l] * inv1; sfm[l] = cum; fmsum += cum; }
        float m2 = s24[12];
        #pragma unroll
        for (int l = 1; l < CL; l++) m2 = fmaxf(m2, s24[12 + l]);
        float e2[CL], sum2 = 0.f;
        #pragma unroll
        for (int l = 0; l < CL; l++) { e2[l] = expf(s24[12 + l] - m2); sum2 += e2[l]; }
        float inv2 = 1.f / sum2, cum2 = 0.f;
        for (int l = CL - 1; l >= 0; l--) { cum2 += e2[l] * inv2; sim[l] = cum2; }
        float dist = 1.f - fmsum / (float)CL;
        g_tmpdis[slot * CB + b] = dist;
        out[CB * COUT + v * CB + b] = dist;
    }
    __syncthreads();

    {
        int l = t >> 5;
        float f  = sigmoidf(xo[24 + t]);
        float i_ = sigmoidf(xo[24 + CHH + t]);
        float o  = sigmoidf(xo[24 + 2 * CHH + t]);
        float ci = tanhf(xo[24 + 3 * CHH + t]);
        float cl = g_c[b * CHH + t];
        float fmv = sfm[l], imv = sim[l], ov = fmv * imv;
        float cnew = ov * (f * cl + i_ * ci) + (fmv - ov) * cl + (imv - ov) * ci;
        float hnew = o * tanhf(cnew);
        g_c[b * CHH + t] = cnew;
        g_h[b * CHH + t] = hnew;
        g_h_all[((size_t)v * CB + b) * CHH + t] = hnew;
    }
    __syncthreads();

    if (t == 0) {
        float cumv[CCS];
        float cum = 0.f;
        #pragma unroll
        for (int k = 0; k < CCS; k++) {
            int s = v - (CCS - 1) + k;
            float d = (s >= 0) ? g_tmpdis[(s % CCS) * CB + b] : 0.f;
            cum += d;
            cumv[k] = cum;
        }
        float mx = cumv[0];
        #pragma unroll
        for (int k = 1; k < CCS; k++) mx = fmaxf(mx, cumv[k]);
        float e[CCS], sum = 0.f;
        #pragma unroll
        for (int k = 0; k < CCS; k++) { e[k] = expf(cumv[k] - mx); sum += e[k]; }
        float inv = 1.f / sum;
        #pragma unroll
        for (int k = 0; k < CCS; k++) sld[k] = e[k] * inv;
    }
    __syncthreads();

    {
        float mh = 0.f;
        float lv[CCS];
        #pragma unroll
        for (int k = 0; k < CCS; k++) {
            int s = v - (CCS - 1) + k;
            float hv = (s >= 0) ? g_h_all[((size_t)s * CB + b) * CHH + t] : 0.f;
            lv[k] = hv * sld[k];
            mh += lv[k];
        }
        float* lp = g_lh_all + ((size_t)v * CB + b) * CKLH + t * CCS;
        #pragma unroll
        for (int k = 0; k < CCS; k++) lp[k] = lv[k];
        smh[t] = mh * (1.f / (float)CCS);
    }
    __syncthreads();

    {
        int j = t & 63, seg = t >> 6;
        float p = 0.f;
        #pragma unroll
        for (int h = 0; h < 64; h++) p += smh[seg * 64 + h] * sw[j * CHH + seg * 64 + h];
        red[seg][j] = p;
    }
    __syncthreads();
    if (t < CHS) {
        float a = sb[t];
        #pragma unroll
        for (int z = 0; z < 6; z++) a += red[z][t];
        ss1[t] = fmaxf(a, 0.f);
    }
    __syncthreads();

    {
        float a = rsb[t];
        #pragma unroll
        for (int j = 0; j < CHS; j++) a += ss1[j] * rsw[t * CHS + j];
        g_theme_all[((size_t)v * CB + b) * CHH + t] = sigmoidf(a);
    }
}

// ---- batched conv GEMM over ALL steps: C[12800][384] = lh_all . cw^T, fused epilogue ----
__global__ __launch_bounds__(256) void k_conv_all(const float* __restrict__ cw,
                                                  const float* __restrict__ cb) {
    __shared__ float As[8][128];
    __shared__ float Bs[8][128];
    const int tid = threadIdx.x;
    const int m0 = blockIdx.x * 128, n0 = blockIdx.y * 128;
    const int tx = tid & 15, ty = tid >> 4;
    const int arow = tid >> 1, ac4 = (tid & 1) * 4;
    float acc[8][8];
    #pragma unroll
    for (int i = 0; i < 8; i++)
        #pragma unroll
        for (int j = 0; j < 8; j++) acc[i][j] = 0.f;

    const float* ap = g_lh_all + (size_t)(m0 + arow) * CKLH + ac4;
    const float* bp = cw + (size_t)(n0 + arow) * CKLH + ac4;
    for (int k0 = 0; k0 < CKLH; k0 += 8) {
        float4 va = *(const float4*)(ap + k0);
        float4 vb = *(const float4*)(bp + k0);
        As[ac4 + 0][arow] = va.x; As[ac4 + 1][arow] = va.y;
        As[ac4 + 2][arow] = va.z; As[ac4 + 3][arow] = va.w;
        Bs[ac4 + 0][arow] = vb.x; Bs[ac4 + 1][arow] = vb.y;
        Bs[ac4 + 2][arow] = vb.z; Bs[ac4 + 3][arow] = vb.w;
        __syncthreads();
        #pragma unroll
        for (int k = 0; k < 8; k++) {
            float4 a0 = *(const float4*)&As[k][ty * 8];
            float4 a1 = *(const float4*)&As[k][ty * 8 + 4];
            float4 c0 = *(const float4*)&Bs[k][tx * 8];
            float4 c1 = *(const float4*)&Bs[k][tx * 8 + 4];
            float av[8] = {a0.x, a0.y, a0.z, a0.w, a1.x, a1.y, a1.z, a1.w};
            float bv[8] = {c0.x, c0.y, c0.z, c0.w, c1.x, c1.y, c1.z, c1.w};
            #pragma unroll
            for (int i = 0; i < 8; i++)
                #pragma unroll
                for (int j = 0; j < 8; j++) acc[i][j] += av[i] * bv[j];
        }
        __syncthreads();
    }
    #pragma unroll
    for (int i = 0; i < 8; i++) {
        int r = m0 + ty * 8 + i;            // r = v*CB + b
        int v = r >> 8, b = r & (CB - 1);
        #pragma unroll
        for (int j = 0; j < 8; j++) {
            int o = n0 + tx * 8 + j;
            float conv = acc[i][j] + cb[o];
            float th = g_theme_all[(size_t)r * CHH + o];
            float hn = g_h_all[(size_t)r * CHH + o];
            g_rnn[((size_t)b * CV + v) * CHH + o] = th * conv + hn;
        }
    }
}

// ---- output GEMM: split-K=24 with atomics ----
__global__ __launch_bounds__(256) void k_out(const float* __restrict__ ow,
                                             float* __restrict__ out) {
    __shared__ float As[8][64];
    __shared__ float Bs[8][128];
    const int tid = threadIdx.x;
    const int m0 = blockIdx.x * 64;
    const int KK = CV * CHH;
    const int kbase = blockIdx.z * (KK / SPLITO);
    const int tx = tid & 15, ty = tid >> 4;
    const int arow = tid >> 2, ac2 = (tid & 3) * 2;
    const int brow = tid >> 1, bc4 = (tid & 1) * 4;
    float acc[4][8];
    #pragma unroll
    for (int i = 0; i < 4; i++)
        #pragma unroll
        for (int j = 0; j < 8; j++) acc[i][j] = 0.f;

    for (int kt = 0; kt < (KK / SPLITO) / 8; kt++) {
        int k0 = kbase + kt * 8;
        float2 va = *(const float2*)(g_rnn + (size_t)(m0 + arow) * KK + k0 + ac2);
        float4 vb = *(const float4*)(ow + (size_t)brow * KK + k0 + bc4);
        As[ac2 + 0][arow] = va.x;
        As[ac2 + 1][arow] = va.y;
        Bs[bc4 + 0][brow] = vb.x; Bs[bc4 + 1][brow] = vb.y;
        Bs[bc4 + 2][brow] = vb.z; Bs[bc4 + 3][brow] = vb.w;
        __syncthreads();
        #pragma unroll
        for (int k = 0; k < 8; k++) {
            float4 a = *(const float4*)&As[k][ty * 4];
            float4 c0 = *(const float4*)&Bs[k][tx * 8];
            float4 c1 = *(const float4*)&Bs[k][tx * 8 + 4];
            float av[4] = {a.x, a.y, a.z, a.w};
            float bv[8] = {c0.x, c0.y, c0.z, c0.w, c1.x, c1.y, c1.z, c1.w};
            #pragma unroll
            for (int i = 0; i < 4; i++)
                #pragma unroll
                for (int j = 0; j < 8; j++) acc[i][j] += av[i] * bv[j];
        }
        __syncthreads();
    }
    #pragma unroll
    for (int i = 0; i < 4; i++) {
        int bb = m0 + ty * 4 + i;
        #pragma unroll
        for (int j = 0; j < 8; j++) {
            atomicAdd(&out[bb * COUT + tx * 8 + j], acc[i][j]);
        }
    }
}

extern "C" void kernel_launch(void* const* d_in, const int* in_sizes, int n_in,
                              void* d_out, int out_size) {
    const int*   node_ids = (const int*)d_in[0];
    const float* time_    = (const float*)d_in[3];
    const float* embed    = (const float*)d_in[6];
    const float* kw  = (const float*)d_in[7];
    const float* kb  = (const float*)d_in[8];
    const float* rw  = (const float*)d_in[9];
    const float* rb  = (const float*)d_in[10];
    const float* sw  = (const float*)d_in[11];
    const float* sb  = (const float*)d_in[12];
    const float* rsw = (const float*)d_in[13];
    const float* rsb = (const float*)d_in[14];
    const float* cw  = (const float*)d_in[15];
    const float* cb  = (const float*)d_in[16];
    const float* ow  = (const float*)d_in[17];
    const float* ob  = (const float*)d_in[18];
    float* out = (float*)d_out;

    k_init<<<(CB * CHH + 255) / 256, 256>>>();
    k_outinit<<<(CB * COUT + 255) / 256, 256>>>(ob, out);
    k_gemm_xo<<<dim3(CB * CV / 128, (CG + 127) / 128), 256>>>(kw, kb, time_, node_ids, embed);
    for (int v = 0; v < CV; v++) {
        k_rec<<<dim3(CB / 32, (CG + 63) / 64), 128>>>(rw, rb, time_, v);
        k_gate<<<CB, CHH>>>(sw, sb, rsw, rsb, v, out);
    }
    k_conv_all<<<dim3(CB * CV / 128, CHH / 128), 256>>>(cw, cb);
    k_out<<<dim3(CB / 64, 1, SPLITO), 256>>>(ow, out);
}